// round 17
// baseline (speedup 1.0000x reference)
#include <cuda_runtime.h>
#include <cuda_bf16.h>
#include <limits.h>

// StreamingRhythmProjector on GB300 — v13: 3-RT pre-kernel (v12) + clean
// v7-shaped hot loop (edge scalars prefetched by thread 0, not deposited
// per-element).
//
// v12 decomposition: short pre-kernel saved ~3us but the per-element edge
// deposit (8 predicates + conditional smem stores) cost the main kernel
// 3.4us. v13 keeps the short pre-kernel and moves the edge fetch to FOUR
// scalar __ldg's by thread 0 at kernel start (independent of the reduction,
// fully overlapped by the other 15 warps' streaming).
//
// Output (f32 flat): speech[B*U] | pause[B*U] | effective[B*U] |
//                    commit[B] | next_phase[B] | next_backlog[B] | next_clock[B]

#define BS 512
#define NW (BS / 32)
#define MAX_ROWS 65536

__device__ static int g_visible[MAX_ROWS];
__device__ static int g_cand[MAX_ROWS];      // pre-soft candidate

__device__ __forceinline__ float warpSum(float v) {
    #pragma unroll
    for (int o = 16; o > 0; o >>= 1) v += __shfl_down_sync(0xffffffffu, v, o);
    return v;
}
__device__ __forceinline__ int warpMin(int v) {
    #pragma unroll
    for (int o = 16; o > 0; o >>= 1) v = min(v, __shfl_down_sync(0xffffffffu, v, o));
    return v;
}

// ---------------------------------------------------------------------------
// Pre-kernel: one warp per row -> g_visible, g_cand. Dependent chain is the
// 3-round binary search only; the open-run probe overlaps it.
// ---------------------------------------------------------------------------
__global__ __launch_bounds__(256)
void precompute_row_stats(const float* __restrict__ unit_mask,
                          const int*   __restrict__ open_run,
                          int B, int U)
{
    const int warp = blockIdx.x * (blockDim.x >> 5) + (threadIdx.x >> 5);
    const int lane = threadIdx.x & 31;
    if (warp >= B) return;
    const size_t base = (size_t)warp * (size_t)U;

    // ---- open probe (first 128 elems) issued before the dependent search ---
    int4 op = make_int4(0, 0, 0, 0);
    const int oi = lane * 4;
    const bool opin = (oi + 3 < U);
    if (opin) op = __ldg((const int4*)(open_run + base + oi));

    // ---- binary search for prefix length (mask monotone 1..1 0..0) ----
    int lo = 0, hi = U;
    while (hi > lo) {
        const int step = (hi - lo + 31) >> 5;
        const int p = lo + lane * step;
        bool one = false;
        if (p < hi) one = (__ldg(unit_mask + base + p) > 0.5f);
        const unsigned ball = __ballot_sync(0xffffffffu, one);
        const int n1 = __popc(ball);
        if (n1 == 0) {
            hi = lo;
        } else {
            const int nl = lo + (n1 - 1) * step + 1;
            const int f0 = lo + n1 * step;
            hi = (f0 < hi) ? f0 : hi;
            lo = nl;
        }
    }
    const int visible = lo;

    // ---- first_open: probe data first, then chunked scan if needed ----
    int fo = INT_MAX;
    if (opin) {
        if (op.x > 0 && oi + 0 < visible) fo = min(fo, oi + 0);
        if (op.y > 0 && oi + 1 < visible) fo = min(fo, oi + 1);
        if (op.z > 0 && oi + 2 < visible) fo = min(fo, oi + 2);
        if (op.w > 0 && oi + 3 < visible) fo = min(fo, oi + 3);
    }
    int first_open = warpMin(fo);
    first_open = __shfl_sync(0xffffffffu, first_open, 0);

    if (first_open == INT_MAX && visible > 128) {
        for (int start = 128; start < visible && first_open == INT_MAX; start += 128) {
            const int idx = start + lane * 4;
            int m = INT_MAX;
            if (idx + 3 < U) {
                const int4 v = __ldg((const int4*)(open_run + base + idx));
                if (v.x > 0 && idx + 0 < visible) m = min(m, idx + 0);
                if (v.y > 0 && idx + 1 < visible) m = min(m, idx + 1);
                if (v.z > 0 && idx + 2 < visible) m = min(m, idx + 2);
                if (v.w > 0 && idx + 3 < visible) m = min(m, idx + 3);
            } else if (idx < U) {
                for (int e = 0; e < 4 && idx + e < U; e++)
                    if (idx + e < visible && __ldg(open_run + base + idx + e) > 0)
                        m = min(m, idx + e);
            }
            int wm = warpMin(m);
            wm = __shfl_sync(0xffffffffu, wm, 0);
            if (wm != INT_MAX) first_open = wm;
        }
    }

    // ---- pre-soft candidate (no prev, no bval) ----
    const bool has_open = (first_open != INT_MAX);
    const int  closed   = has_open ? first_open : visible;
    const int  cap      = max(visible - 2, 0);     // TAIL_HOLD_UNITS
    const int  cand     = min(cap, closed);

    if (lane == 0) {
        g_visible[warp] = visible;
        g_cand[warp]    = cand;
    }
}

// ---------------------------------------------------------------------------
// Main streaming kernel: ONE reduction barrier; thread 0 prefetches the
// edge scalars at index cand-1. U % 4 == 0, U <= BS*4.
// ---------------------------------------------------------------------------
__global__ __launch_bounds__(BS, 4)
void rhythm_projector_v13(
    const float* __restrict__ anchor_src,
    const float* __restrict__ speech_budget,
    const float* __restrict__ pause_budget,
    const float* __restrict__ lr_unit,
    const float* __restrict__ pw_unit,
    const float* __restrict__ bl_unit,
    const float* __restrict__ phase_ptr,
    const float* __restrict__ backlog,
    const float* __restrict__ clock_delta,
    const int*   __restrict__ commit_frontier,
    float* __restrict__ out,
    int B, int U)
{
    const int row = blockIdx.x;
    const int tid = threadIdx.x;
    const size_t base = (size_t)row * (size_t)U;
    const size_t BU = (size_t)B * (size_t)U;

    __shared__ float s_red[5][NW];
    __shared__ float s_bcast[5];
    __shared__ float s_edge[4];   // sp, sc, ar, bl at index cand-1 (thread 0 only)

    const int visible = g_visible[row];
    const int cand    = g_cand[row];
    const int prev    = commit_frontier[row];
    const int C1      = max(prev, cand);          // window upper bound (pre-soft)

    // -------- thread 0: prefetch edge scalars (independent of reduction) ----
    if (tid == 0 && cand > 0) {
        const int eidx = cand - 1;
        const float blv = __ldg(bl_unit    + base + eidx);
        const float arv = __ldg(anchor_src + base + eidx);
        const float lrv = __ldg(lr_unit    + base + eidx);
        const float pwv = __ldg(pw_unit    + base + eidx);
        const float a = fmaxf(arv, 1.0f);
        s_edge[0] = fmaxf(fminf(a * __expf(lrv), a * 3.0f), 1.0f);  // sp_edge
        s_edge[1] = fmaxf(pwv, 0.f) * (0.5f + blv);                 // sc_edge
        s_edge[2] = arv;                                            // ar_edge
        s_edge[3] = blv;                                            // bval
    }

    const int j = tid * 4;
    const bool in = (j < U);

    // -------- Pass A: loads + elementwise + all partial sums (v7 shape) ------
    float4 spv = make_float4(0.f, 0.f, 0.f, 0.f);
    float4 scv = spv;
    float sum_sp = 0.f, sum_sc = 0.f, win_sp = 0.f, win_sc = 0.f, win_ar = 0.f;
    if (in) {
        const float4 ar = __ldcs((const float4*)(anchor_src + base + j));
        const float4 lr = __ldcs((const float4*)(lr_unit    + base + j));
        const float4 pw = __ldcs((const float4*)(pw_unit    + base + j));
        const float4 bl = __ldcs((const float4*)(bl_unit    + base + j));

        #define ELEMA(c, e)                                                   \
        {                                                                     \
            const int je = j + (e);                                           \
            if (je < visible) {                                               \
                const float a  = fmaxf(ar.c, 1.0f);                           \
                const float bb = a * __expf(lr.c);                            \
                spv.c = fmaxf(fminf(bb, a * 3.0f), 1.0f);                     \
                scv.c = fmaxf(pw.c, 0.f) * (0.5f + bl.c);                     \
                sum_sp += spv.c; sum_sc += scv.c;                             \
                if (je >= prev && je < C1) {                                  \
                    win_sp += spv.c; win_sc += scv.c; win_ar += ar.c;         \
                }                                                             \
            }                                                                 \
        }
        ELEMA(x, 0) ELEMA(y, 1) ELEMA(z, 2) ELEMA(w, 3)
        #undef ELEMA
    }

    // -------- single block reduction (5 floats) ------------------------------
    {
        const int wid = tid >> 5, lid = tid & 31;
        float a0 = warpSum(sum_sp);
        float a1 = warpSum(sum_sc);
        float a2 = warpSum(win_sp);
        float a3 = warpSum(win_sc);
        float a4 = warpSum(win_ar);
        if (lid == 0) {
            s_red[0][wid] = a0; s_red[1][wid] = a1; s_red[2][wid] = a2;
            s_red[3][wid] = a3; s_red[4][wid] = a4;
        }
        __syncthreads();
        if (wid == 0) {
            float v0 = (lid < NW) ? s_red[0][lid] : 0.f;
            float v1 = (lid < NW) ? s_red[1][lid] : 0.f;
            float v2 = (lid < NW) ? s_red[2][lid] : 0.f;
            float v3 = (lid < NW) ? s_red[3][lid] : 0.f;
            float v4 = (lid < NW) ? s_red[4][lid] : 0.f;
            #pragma unroll
            for (int o = 8; o > 0; o >>= 1) {
                v0 += __shfl_down_sync(0xffffffffu, v0, o);
                v1 += __shfl_down_sync(0xffffffffu, v1, o);
                v2 += __shfl_down_sync(0xffffffffu, v2, o);
                v3 += __shfl_down_sync(0xffffffffu, v3, o);
                v4 += __shfl_down_sync(0xffffffffu, v4, o);
            }
            if (lid == 0) {
                s_bcast[0] = v0; s_bcast[1] = v1; s_bcast[2] = v2;
                s_bcast[3] = v3; s_bcast[4] = v4;
            }
        }
        __syncthreads();
        sum_sp = s_bcast[0]; sum_sc = s_bcast[1];
        win_sp = s_bcast[2]; win_sc = s_bcast[3]; win_ar = s_bcast[4];
    }

    // -------- scalar logic (uniform across block) ----------------------------
    const float sbud = speech_budget[row];
    const float pbud = pause_budget[row];
    const float speech_scale = sbud / fmaxf(sum_sp, 1e-6f);
    const bool  use_scores = (sum_sc > 0.f);
    const float wdenom = pbud / fmaxf(sum_sc, 1e-6f);
    const float fb     = pbud / fmaxf((float)visible, 1.f);

    // -------- compute + 3 streaming stores (no further reduction) ------------
    if (in) {
        float4 speech, pause, eff;
        #define ELEMB(c, e)                                                \
        {                                                                  \
            const bool vis = ((j + (e)) < visible);                        \
            speech.c = vis ? (spv.c * speech_scale) : 0.f;                 \
            pause.c  = vis ? (use_scores ? (scv.c * wdenom) : fb) : 0.f;   \
            eff.c = speech.c + pause.c;                                    \
        }
        ELEMB(x, 0) ELEMB(y, 1) ELEMB(z, 2) ELEMB(w, 3)
        #undef ELEMB

        __stcs((float4*)(out + base + j),          speech);
        __stcs((float4*)(out + BU + base + j),     pause);
        __stcs((float4*)(out + 2 * BU + base + j), eff);
    }

    // -------- tail outputs (thread 0): soft decision + edge adjustment -------
    if (tid == 0) {
        // s_edge written and read by thread 0 only (no sync needed); only
        // consumed when cand > 0.
        const float bval = s_edge[3];
        const bool soft = (cand > 0) && (cand < visible) && (bval < 0.45f);
        const int commit = soft ? max(prev, cand - 1) : max(prev, cand);

        float wsp = win_sp, wsc = win_sc, war = win_ar;
        if (soft && (cand - 1) >= prev) {
            // edge element cand-1 was inside the accumulated window; remove it
            wsp -= s_edge[0]; wsc -= s_edge[1]; war -= s_edge[2];
        }

        const float exec_s = speech_scale * wsp +
                             (use_scores ? (wdenom * wsc)
                                         : (fb * (float)(commit - prev)));
        const bool adv = commit > prev;
        const float cd = clock_delta[row];
        const float next_clock = adv ? (cd + (exec_s - war)) : cd;
        const float next_backlog = adv ? fmaxf(next_clock, 0.f) : backlog[row];
        // effective.sum == sbud + pbud analytically (speech renormalized to
        // its budget; pause weights sum to 1). Only consumed when adv.
        const float vt = fmaxf(sbud + pbud, 1.f);
        float next_phase = phase_ptr[row];
        if (adv) next_phase = fminf(fmaxf(next_phase + exec_s / vt, 0.f), 1.f);

        float* tail = out + 3 * BU;
        tail[row]         = (float)commit;
        tail[B + row]     = next_phase;
        tail[2 * B + row] = next_backlog;
        tail[3 * B + row] = next_clock;
    }
}

// ---------------------------------------------------------------------------
// Scalar fallback kernel (any shape; self-contained, no prefix assumption)
// ---------------------------------------------------------------------------
template<int ITEMS>
__global__ __launch_bounds__(BS)
void rhythm_projector_scalar(
    const float* __restrict__ anchor_src,
    const float* __restrict__ unit_mask,
    const float* __restrict__ speech_budget,
    const float* __restrict__ pause_budget,
    const float* __restrict__ lr_unit,
    const float* __restrict__ pw_unit,
    const float* __restrict__ bl_unit,
    const float* __restrict__ phase_ptr,
    const float* __restrict__ backlog,
    const float* __restrict__ clock_delta,
    const int*   __restrict__ commit_frontier,
    const int*   __restrict__ open_run,
    float* __restrict__ out,
    int B, int U)
{
    const int row = blockIdx.x;
    const int tid = threadIdx.x;
    const size_t base = (size_t)row * (size_t)U;
    const size_t BU = (size_t)B * (size_t)U;

    __shared__ float s_f0[NW], s_f1[NW], s_f2[NW];
    __shared__ int   s_i0[NW];
    __shared__ float s_bcast[3];
    __shared__ int   s_ibcast;

    float sp[ITEMS], sc[ITEMS], msk[ITEMS];
    float sum_sp = 0.f, sum_sc = 0.f, sum_m = 0.f;
    int first_open = INT_MAX;

    #pragma unroll
    for (int k = 0; k < ITEMS; k++) {
        const int j = k * BS + tid;
        float m = 0.f, spv = 0.f, scv = 0.f;
        if (j < U) {
            const float arv = anchor_src[base + j];
            m               = unit_mask[base + j];
            const float lrv = lr_unit[base + j];
            const float pwv = pw_unit[base + j];
            const float blv = bl_unit[base + j];
            const int   opv = open_run[base + j];
            const float a   = fmaxf(arv, 1.0f);
            const float b   = a * __expf(lrv);
            spv = fmaxf(fminf(b, a * 3.0f), 1.0f) * m;
            scv = fmaxf(pwv, 0.f) * (0.5f + blv) * m;
            if (opv > 0 && m > 0.f) first_open = min(first_open, j);
        }
        sp[k] = spv; sc[k] = scv; msk[k] = m;
        sum_sp += spv; sum_sc += scv; sum_m += m;
    }

    {
        float w0 = warpSum(sum_sp), w1 = warpSum(sum_sc), w2 = warpSum(sum_m);
        int w3 = warpMin(first_open);
        const int wid = tid >> 5, lid = tid & 31;
        if (lid == 0) { s_f0[wid] = w0; s_f1[wid] = w1; s_f2[wid] = w2; s_i0[wid] = w3; }
        __syncthreads();
        if (wid == 0) {
            float v0 = (lid < NW) ? s_f0[lid] : 0.f;
            float v1 = (lid < NW) ? s_f1[lid] : 0.f;
            float v2 = (lid < NW) ? s_f2[lid] : 0.f;
            int   v3 = (lid < NW) ? s_i0[lid] : INT_MAX;
            #pragma unroll
            for (int o = 8; o > 0; o >>= 1) {
                v0 += __shfl_down_sync(0xffffffffu, v0, o);
                v1 += __shfl_down_sync(0xffffffffu, v1, o);
                v2 += __shfl_down_sync(0xffffffffu, v2, o);
                v3 = min(v3, __shfl_down_sync(0xffffffffu, v3, o));
            }
            if (lid == 0) { s_bcast[0] = v0; s_bcast[1] = v1; s_bcast[2] = v2; s_ibcast = v3; }
        }
        __syncthreads();
        sum_sp = s_bcast[0]; sum_sc = s_bcast[1]; sum_m = s_bcast[2];
        first_open = s_ibcast;
    }

    const float sbud = speech_budget[row];
    const float pbud = pause_budget[row];
    const float speech_scale = sbud / fmaxf(sum_sp, 1e-6f);
    const int  visible  = (int)sum_m;
    const bool has_open = (first_open != INT_MAX);
    const int  closed   = has_open ? first_open : visible;
    const int  cap      = max(visible - 2, 0);
    int cand = min(cap, closed);
    const int prev = commit_frontier[row];
    const int bidx = min(max(cand - 1, 0), U - 1);
    const float bval = __ldg(bl_unit + base + bidx);
    const bool soft = (cand > 0) && (cand < visible) && (bval < 0.45f);
    if (soft) cand = max(prev, cand - 1);
    const int commit = max(prev, cand);

    const bool  use_scores = (sum_sc > 0.f);
    const float wdenom = 1.f / fmaxf(sum_sc, 1e-6f);
    const float fb     = 1.f / fmaxf(sum_m, 1.f);

    float sum_eff = 0.f, exec_s = 0.f, src_s = 0.f;
    #pragma unroll
    for (int k = 0; k < ITEMS; k++) {
        const int j = k * BS + tid;
        if (j < U) {
            const float speech = sp[k] * speech_scale;
            const float w      = use_scores ? (sc[k] * wdenom) : (msk[k] * fb);
            const float pause  = w * pbud;
            const float eff    = (speech + pause) * msk[k];
            out[base + j]          = speech;
            out[BU + base + j]     = pause;
            out[2 * BU + base + j] = eff;
            sum_eff += eff;
            if (j >= prev && j < commit) {
                exec_s += eff;
                src_s  += __ldg(anchor_src + base + j);
            }
        }
    }

    {
        float w0 = warpSum(sum_eff), w1 = warpSum(exec_s), w2 = warpSum(src_s);
        const int wid = tid >> 5, lid = tid & 31;
        __syncthreads();
        if (lid == 0) { s_f0[wid] = w0; s_f1[wid] = w1; s_f2[wid] = w2; }
        __syncthreads();
        if (tid == 0) {
            float v0 = 0.f, v1 = 0.f, v2 = 0.f;
            #pragma unroll
            for (int i = 0; i < NW; i++) { v0 += s_f0[i]; v1 += s_f1[i]; v2 += s_f2[i]; }
            const bool adv = commit > prev;
            const float cd = clock_delta[row];
            const float next_clock = adv ? (cd + (v1 - v2)) : cd;
            const float next_backlog = adv ? fmaxf(next_clock, 0.f) : backlog[row];
            const float vt = fmaxf(v0, 1.f);
            float next_phase = phase_ptr[row];
            if (adv) next_phase = fminf(fmaxf(next_phase + v1 / vt, 0.f), 1.f);
            float* tail = out + 3 * BU;
            tail[row]         = (float)commit;
            tail[B + row]     = next_phase;
            tail[2 * B + row] = next_backlog;
            tail[3 * B + row] = next_clock;
        }
    }
}

extern "C" void kernel_launch(void* const* d_in, const int* in_sizes, int n_in,
                              void* d_out, int out_size)
{
    const float* anchor_src  = (const float*)d_in[0];
    const float* unit_mask   = (const float*)d_in[1];
    const float* sbud        = (const float*)d_in[2];
    const float* pbud        = (const float*)d_in[3];
    const float* lr_unit     = (const float*)d_in[4];
    const float* pw_unit     = (const float*)d_in[5];
    const float* bl_unit     = (const float*)d_in[6];
    const float* phase_ptr   = (const float*)d_in[7];
    const float* backlog     = (const float*)d_in[8];
    const float* clock_delta = (const float*)d_in[9];
    const int*   frontier    = (const int*)d_in[10];
    const int*   open_run    = (const int*)d_in[11];
    float* out = (float*)d_out;

    const int B = in_sizes[2];            // speech_budget_win has B elements
    const int U = in_sizes[0] / B;        // dur_anchor_src has B*U

    if ((U & 3) == 0 && U <= BS * 4 && B <= MAX_ROWS) {
        const int preBlocks = (B + 7) / 8;        // 8 warps / 256-thread block
        precompute_row_stats<<<preBlocks, 256>>>(unit_mask, open_run, B, U);
        rhythm_projector_v13<<<B, BS>>>(anchor_src, sbud, pbud, lr_unit,
            pw_unit, bl_unit, phase_ptr, backlog, clock_delta, frontier, out,
            B, U);
    } else {
        const int items = (U + BS - 1) / BS;
        dim3 grid(B), block(BS);
        #define LAUNCH(N) rhythm_projector_scalar<N><<<grid, block>>>(anchor_src,    \
            unit_mask, sbud, pbud, lr_unit, pw_unit, bl_unit, phase_ptr, backlog,    \
            clock_delta, frontier, open_run, out, B, U)
        if      (items <= 4)  LAUNCH(4);
        else if (items <= 8)  LAUNCH(8);
        else if (items <= 16) LAUNCH(16);
        else                  LAUNCH(32);
        #undef LAUNCH
    }
}